// round 17
// baseline (speedup 1.0000x reference)
#include <cuda_runtime.h>
#include <cstdint>

#define NFEAT 6272
#define MMEM  50000
#define CDIM  1024
#define BIMG  8
#define FHW   28
#define IMG   224
#define NPIX  (BIMG*IMG*IMG)

#define MTILE 128
#define NTILE 128
#define NTILES 391
#define MPAD2 (NTILES*NTILE)     // 50048
#define KCHB  128                // int8 elems (=bytes) per K chunk = 128B rows
#define NCHUNKS (CDIM/KCHB)      // 8
#define NSTAGE 2

// SW128-swizzled 128B rows: no padding, conflict-free ldmatrix
#define ROWB   128
#define STAGEB (MTILE*ROWB)                // 16384 per operand per stage
#define SBBASE (NSTAGE*STAGEB)             // 32768
#define AUX_OFF (2*NSTAGE*STAGEB)          // 65536 (rel. to aligned base)
#define SMEM_TOTAL (1024 + AUX_OFF + 512*5)  // align + tiles + m2s/f2s/sred/sas/sbs

// ---- static device scratch ----
__device__ float g_f2[NFEAT];
__device__ float g_m2[MPAD2];
__device__ float g_saf[NFEAT];
__device__ float g_sbm[MPAD2];
__device__ unsigned int g_minbits[NFEAT];
__device__ float g_gauss[17];
__device__ float g_resized[NPIX];
__device__ float g_tmpb[NPIX];
__device__ signed char g_qf[NFEAT*CDIM];
__device__ signed char g_qm[(size_t)MPAD2*CDIM];

static __device__ __forceinline__ uint32_t smem_u32(const void* p){
    uint32_t a; asm("{ .reg .u64 t; cvta.to.shared.u64 t, %1; cvt.u32.u64 %0, t; }"
                    : "=r"(a) : "l"(p));
    return a;
}
static __device__ __forceinline__ void cp16(uint32_t dst, const void* src){
    asm volatile("cp.async.cg.shared.global [%0], [%1], 16;" :: "r"(dst), "l"(src) : "memory");
}
static __device__ __forceinline__ void ldsm4(uint32_t p, uint32_t &r0, uint32_t &r1,
                                             uint32_t &r2, uint32_t &r3){
    asm volatile("ldmatrix.sync.aligned.m8n8.x4.shared.b16 {%0,%1,%2,%3}, [%4];"
                 : "=r"(r0), "=r"(r1), "=r"(r2), "=r"(r3) : "r"(p));
}
// s8 x s8 -> s32 accumulate, K=32 per instruction
static __device__ __forceinline__ void mma_s8(int* c, uint32_t a0, uint32_t a1,
                                              uint32_t a2, uint32_t a3,
                                              uint32_t b0, uint32_t b1){
    asm volatile("mma.sync.aligned.m16n8k32.row.col.s32.s8.s8.s32 "
                 "{%0,%1,%2,%3},{%4,%5,%6,%7},{%8,%9},{%0,%1,%2,%3};"
                 : "+r"(c[0]), "+r"(c[1]), "+r"(c[2]), "+r"(c[3])
                 : "r"(a0), "r"(a1), "r"(a2), "r"(a3), "r"(b0), "r"(b1));
}

// ---------------------------------------------------------------------------
__global__ void k_init(){
    int tid = blockIdx.x * blockDim.x + threadIdx.x;
    if (tid < NFEAT) g_minbits[tid] = 0x7F7FFFFFu;
    if (tid < 17){
        float s = 0.f;
        #pragma unroll
        for (int t = 0; t < 17; t++){ float d = (float)t - 8.f; s += expf(-(d*d)/32.f); }
        float d = (float)tid - 8.f;
        g_gauss[tid] = expf(-(d*d)/32.f) / s;
    }
}

// ---------------------------------------------------------------------------
// fused fp32 -> int8 row quantization + squared row norm (fp32 exact).
// one warp per row; q = round(127*x/maxabs), scale = maxabs/127.
// ---------------------------------------------------------------------------
__global__ void k_prep(const float* __restrict__ X, int nrows, int nvalid, int mode){
    int warp = (blockIdx.x * blockDim.x + threadIdx.x) >> 5;
    int lane = threadIdx.x & 31;
    if (warp >= nrows) return;
    uint32_t* dst = (uint32_t*)((mode == 0 ? g_qf : g_qm) + (size_t)warp * CDIM);
    if (warp >= nvalid){
        #pragma unroll
        for (int j = 0; j < 8; j++) dst[j*32 + lane] = 0u;
        if (lane == 0){ g_m2[warp] = __int_as_float(0x7F800000); g_sbm[warp] = 0.f; }
        return;
    }
    const float4* src = (const float4*)(X + (size_t)warp * CDIM);
    float4 v[8];
    float s = 0.f, m = 0.f;
    #pragma unroll
    for (int j = 0; j < 8; j++){
        v[j] = src[j*32 + lane];
        s += v[j].x*v[j].x + v[j].y*v[j].y + v[j].z*v[j].z + v[j].w*v[j].w;
        m = fmaxf(m, fmaxf(fmaxf(fabsf(v[j].x), fabsf(v[j].y)),
                           fmaxf(fabsf(v[j].z), fabsf(v[j].w))));
    }
    #pragma unroll
    for (int o = 16; o > 0; o >>= 1){
        s += __shfl_xor_sync(0xFFFFFFFFu, s, o);
        m = fmaxf(m, __shfl_xor_sync(0xFFFFFFFFu, m, o));
    }
    const float inv = (m > 0.f) ? (127.f / m) : 0.f;
    #pragma unroll
    for (int j = 0; j < 8; j++){
        int q0 = __float2int_rn(v[j].x * inv);
        int q1 = __float2int_rn(v[j].y * inv);
        int q2 = __float2int_rn(v[j].z * inv);
        int q3 = __float2int_rn(v[j].w * inv);
        dst[j*32 + lane] = (uint32_t)(q0 & 255) | ((uint32_t)(q1 & 255) << 8) |
                           ((uint32_t)(q2 & 255) << 16) | ((uint32_t)(q3 & 255) << 24);
    }
    if (lane == 0){
        float sc = (m > 0.f) ? (m / 127.f) : 0.f;
        if (mode == 0){ g_f2[warp] = s; g_saf[warp] = sc; }
        else          { g_m2[warp] = s; g_sbm[warp] = sc; }
    }
}

// ---------------------------------------------------------------------------
// int8 IMMA distance GEMM + min epilogue.
// CTA 128x128, 8 warps (2M x 4N), warp tile 64x32, 2 CTAs/SM.
// KCHB=128: 8 barrier regions, 4 k32 steps/region, fragment ping-pong,
// 2-stage SW128-swizzled smem ring, wait_group 0 at region top.
// s8 m16n8k32 fragments are byte-identical to f16 m16n8k16 -> same ldmatrix.
// ---------------------------------------------------------------------------
__global__ __launch_bounds__(256, 2)
void k_gemm_tc(){
    extern __shared__ char smraw[];
    const uint32_t rawb = smem_u32(smraw);
    const uint32_t sbase = (rawb + 1023u) & ~1023u;      // 1KB-align for swizzle
    char* smal = smraw + (sbase - rawb);
    const int tid = threadIdx.x;
    const int wid = tid >> 5, lane = tid & 31;
    const int warpM = wid >> 2, warpN = wid & 3;
    const int rowBase = blockIdx.x * MTILE;
    const int colBase = blockIdx.y * NTILE;

    float* m2s = (float*)(smal + AUX_OFF);
    float* f2s = (float*)(smal + AUX_OFF + 512);
    unsigned int* sred = (unsigned int*)(smal + AUX_OFF + 1024);
    float* sas = (float*)(smal + AUX_OFF + 1536);
    float* sbs = (float*)(smal + AUX_OFF + 2048);
    if (tid < 128){
        m2s[tid] = g_m2[colBase + tid];
        f2s[tid] = g_f2[rowBase + tid];
        sred[tid] = 0x7F7FFFFFu;
        sas[tid] = g_saf[rowBase + tid];
        sbs[tid] = g_sbm[colBase + tid];
    }

    // ---- per-thread cp.async endpoints: rows r0+32t (t=0..3), swizzled dst ----
    const int r0 = tid >> 3, seg = tid & 7;
    const char* aSrc = (const char*)g_qf + ((size_t)(rowBase + r0))*CDIM + seg*16;
    const char* bSrc = (const char*)g_qm + ((size_t)(colBase + r0))*CDIM + seg*16;
    const uint32_t wsw = (uint32_t)((seg*16) ^ ((r0 & 7) << 4));   // (r0+32t)&7 == r0&7
    const uint32_t aDst = sbase + r0*ROWB + wsw;
    const uint32_t bDst = aDst + SBBASE;

    #define ISSUE(ks, st) do { \
        const size_t _ko = (size_t)(ks) * KCHB; \
        const uint32_t _so = (uint32_t)((st) * STAGEB); \
        _Pragma("unroll") \
        for (int t = 0; t < 4; t++){ \
            cp16(aDst + _so + t*(32*ROWB), aSrc + _ko + (size_t)t*(32*CDIM)); \
            cp16(bDst + _so + t*(32*ROWB), bSrc + _ko + (size_t)t*(32*CDIM)); \
        } \
        asm volatile("cp.async.commit_group;" ::: "memory"); \
    } while(0)

    // ---- LDSM row bases + per-step swizzled in-row offsets (k32 = 32 bytes) ----
    const int lrow = lane & 15;
    const int lcol16 = (lane >> 4) & 1;
    const uint32_t lsw = (uint32_t)((lrow & 7) << 4);   // row&7 invariant to mi*16
    const uint32_t o0 = (uint32_t)((0*32 + lcol16*16)) ^ lsw;
    const uint32_t o1 = (uint32_t)((1*32 + lcol16*16)) ^ lsw;
    const uint32_t o2 = (uint32_t)((2*32 + lcol16*16)) ^ lsw;
    const uint32_t o3 = (uint32_t)((3*32 + lcol16*16)) ^ lsw;
    const uint32_t aRow = sbase + (warpM*64 + lrow)*ROWB;
    const uint32_t bRow = sbase + SBBASE + (warpN*32 + lrow)*ROWB;

    uint32_t fa[2][4][4], fb[2][2][4];
    #define LOAD_FRAGS(buf, ap, bp) do { \
        _Pragma("unroll") \
        for (int mi = 0; mi < 4; mi++) \
            ldsm4((ap) + mi*(16*ROWB), fa[buf][mi][0], fa[buf][mi][1], \
                  fa[buf][mi][2], fa[buf][mi][3]); \
        _Pragma("unroll") \
        for (int nh = 0; nh < 2; nh++) \
            ldsm4((bp) + nh*(16*ROWB), fb[buf][nh][0], fb[buf][nh][1], \
                  fb[buf][nh][2], fb[buf][nh][3]); \
    } while(0)

    #define MMA_STEP(buf) do { \
        _Pragma("unroll") \
        for (int mi = 0; mi < 4; mi++) \
            _Pragma("unroll") \
            for (int ni = 0; ni < 4; ni++){ \
                int nh = ni >> 1, od = ni & 1; \
                mma_s8(acc[mi][ni], fa[buf][mi][0], fa[buf][mi][1], \
                       fa[buf][mi][2], fa[buf][mi][3], \
                       fb[buf][nh][od], fb[buf][nh][od + 2]); \
            } \
    } while(0)

    int acc[4][4][4];
    #pragma unroll
    for (int mi = 0; mi < 4; mi++)
        #pragma unroll
        for (int ni = 0; ni < 4; ni++)
            #pragma unroll
            for (int k = 0; k < 4; k++) acc[mi][ni][k] = 0;

    // prologue: chunk 0 in flight
    ISSUE(0, 0);
    asm volatile("cp.async.wait_group 0;" ::: "memory");
    __syncthreads();

    #pragma unroll
    for (int ks = 0; ks < NCHUNKS; ks++){
        const int st = ks & 1;
        if (ks > 0){
            asm volatile("cp.async.wait_group 0;" ::: "memory");
            __syncthreads();
        }
        if (ks + 1 < NCHUNKS) ISSUE(ks + 1, st ^ 1);

        const uint32_t ao = aRow + (uint32_t)(st * STAGEB);
        const uint32_t bo = bRow + (uint32_t)(st * STAGEB);
        // 4 k32 steps with fragment ping-pong (all reads within resident stage)
        LOAD_FRAGS(0, ao + o0, bo + o0);
        LOAD_FRAGS(1, ao + o1, bo + o1);
        MMA_STEP(0);
        LOAD_FRAGS(0, ao + o2, bo + o2);
        MMA_STEP(1);
        LOAD_FRAGS(1, ao + o3, bo + o3);
        MMA_STEP(0);
        MMA_STEP(1);
    }
    #undef ISSUE
    #undef LOAD_FRAGS
    #undef MMA_STEP

    // ---- epilogue: d2 = f2 + m2 - 2*sa*sb*dot_int, min-reduce ----
    {
        const int q = lane >> 2;        // row-in-8 group
        const int ql = lane & 3;        // col pair selector
        float m2v[4][2], sbv[4][2], f2lo[4], f2hi[4], salo[4], sahi[4];
        #pragma unroll
        for (int ni = 0; ni < 4; ni++){
            int c = warpN*32 + ni*8 + 2*ql;
            m2v[ni][0] = m2s[c];   m2v[ni][1] = m2s[c + 1];
            sbv[ni][0] = sbs[c];   sbv[ni][1] = sbs[c + 1];
        }
        #pragma unroll
        for (int mi = 0; mi < 4; mi++){
            int r = warpM*64 + mi*16 + q;
            f2lo[mi] = f2s[r];      f2hi[mi] = f2s[r + 8];
            salo[mi] = -2.f*sas[r]; sahi[mi] = -2.f*sas[r + 8];
        }
        #pragma unroll
        for (int mi = 0; mi < 4; mi++){
            float vlo = __int_as_float(0x7F800000);
            float vhi = vlo;
            #pragma unroll
            for (int ni = 0; ni < 4; ni++){
                vlo = fminf(vlo, fminf(
                    fmaf(salo[mi]*sbv[ni][0], (float)acc[mi][ni][0], f2lo[mi] + m2v[ni][0]),
                    fmaf(salo[mi]*sbv[ni][1], (float)acc[mi][ni][1], f2lo[mi] + m2v[ni][1])));
                vhi = fminf(vhi, fminf(
                    fmaf(sahi[mi]*sbv[ni][0], (float)acc[mi][ni][2], f2hi[mi] + m2v[ni][0]),
                    fmaf(sahi[mi]*sbv[ni][1], (float)acc[mi][ni][3], f2hi[mi] + m2v[ni][1])));
            }
            #pragma unroll
            for (int o = 1; o < 4; o <<= 1){
                vlo = fminf(vlo, __shfl_xor_sync(0xFFFFFFFFu, vlo, o));
                vhi = fminf(vhi, __shfl_xor_sync(0xFFFFFFFFu, vhi, o));
            }
            if (ql == 0){
                int r = warpM*64 + mi*16 + q;
                atomicMin(&sred[r],     __float_as_uint(fmaxf(vlo, 0.f)));
                atomicMin(&sred[r + 8], __float_as_uint(fmaxf(vhi, 0.f)));
            }
        }
    }
    __syncthreads();
    if (tid < 128)
        atomicMin(&g_minbits[rowBase + tid], sred[tid]);
}

// ---------------------------------------------------------------------------
__global__ void k_scores(float* __restrict__ out){
    __shared__ unsigned int red[256];
    const int b = blockIdx.x;
    unsigned int mb = 0u;
    for (int i = threadIdx.x; i < FHW*FHW; i += 256)
        mb = max(mb, g_minbits[b*FHW*FHW + i]);
    red[threadIdx.x] = mb; __syncthreads();
    for (int s = 128; s > 0; s >>= 1){
        if (threadIdx.x < s) red[threadIdx.x] = max(red[threadIdx.x], red[threadIdx.x + s]);
        __syncthreads();
    }
    if (threadIdx.x == 0) out[b] = sqrtf(__uint_as_float(red[0]));
}

__global__ void k_resize(){
    int idx = blockIdx.x * blockDim.x + threadIdx.x;
    if (idx >= NPIX) return;
    int x = idx % IMG, y = (idx / IMG) % IMG, b = idx / (IMG*IMG);
    float fy = y * 0.125f - 0.4375f;
    float fx = x * 0.125f - 0.4375f;
    float fy0 = floorf(fy), fx0 = floorf(fx);
    float wy = fy - fy0, wx = fx - fx0;
    int y0 = max((int)fy0, 0), y1 = min((int)fy0 + 1, FHW-1);
    int x0 = max((int)fx0, 0), x1 = min((int)fx0 + 1, FHW-1);
    const unsigned int* mb = g_minbits + b*FHW*FHW;
    float s00 = sqrtf(__uint_as_float(mb[y0*FHW + x0]));
    float s01 = sqrtf(__uint_as_float(mb[y0*FHW + x1]));
    float s10 = sqrtf(__uint_as_float(mb[y1*FHW + x0]));
    float s11 = sqrtf(__uint_as_float(mb[y1*FHW + x1]));
    g_resized[idx] = (1.f-wy)*((1.f-wx)*s00 + wx*s01) + wy*((1.f-wx)*s10 + wx*s11);
}

__global__ void k_blurh(){
    __shared__ float w[17];
    if (threadIdx.x < 17) w[threadIdx.x] = g_gauss[threadIdx.x];
    __syncthreads();
    int idx = blockIdx.x * blockDim.x + threadIdx.x;
    if (idx >= NPIX) return;
    int x = idx % IMG, y = (idx / IMG) % IMG, b = idx / (IMG*IMG);
    const float* img = g_resized + b*IMG*IMG;
    float s = 0.f;
    #pragma unroll
    for (int t = 0; t < 17; t++){
        int yy = y - 8 + t;
        yy = (yy < 0) ? -yy : yy;
        yy = (yy > IMG-1) ? 2*(IMG-1) - yy : yy;
        s += w[t] * img[yy*IMG + x];
    }
    g_tmpb[idx] = s;
}

__global__ void k_blurv(float* __restrict__ out){
    __shared__ float w[17];
    if (threadIdx.x < 17) w[threadIdx.x] = g_gauss[threadIdx.x];
    __syncthreads();
    int idx = blockIdx.x * blockDim.x + threadIdx.x;
    if (idx >= NPIX) return;
    int x = idx % IMG, y = (idx / IMG) % IMG, b = idx / (IMG*IMG);
    const float* img = g_tmpb + b*IMG*IMG;
    float s = 0.f;
    #pragma unroll
    for (int t = 0; t < 17; t++){
        int xx = x - 8 + t;
        xx = (xx < 0) ? -xx : xx;
        xx = (xx > IMG-1) ? 2*(IMG-1) - xx : xx;
        s += w[t] * img[y*IMG + xx];
    }
    out[BIMG + idx] = s;
}

// ---------------------------------------------------------------------------
extern "C" void kernel_launch(void* const* d_in, const int* in_sizes, int n_in,
                              void* d_out, int out_size){
    const float* feat = (const float*)d_in[0];
    const float* mem  = (const float*)d_in[1];
    if (n_in >= 2 && in_sizes[0] == MMEM * CDIM){
        const float* t = feat; feat = mem; mem = t;
    }
    float* out = (float*)d_out;

    cudaFuncSetAttribute(k_gemm_tc, cudaFuncAttributeMaxDynamicSharedMemorySize, SMEM_TOTAL);

    k_init<<<(NFEAT + 255)/256, 256>>>();
    k_prep<<<NFEAT/8, 256>>>(feat, NFEAT, NFEAT, 0);
    k_prep<<<MPAD2/8, 256>>>(mem, MPAD2, MMEM, 1);

    dim3 g(NFEAT/MTILE, NTILES);   // 49 x 391, x fastest -> B tile L2 reuse
    k_gemm_tc<<<g, 256, SMEM_TOTAL>>>();

    k_scores<<<BIMG, 256>>>(out);
    int pb = (NPIX + 255)/256;
    k_resize<<<pb, 256>>>();
    k_blurh<<<pb, 256>>>();
    k_blurv<<<pb, 256>>>(out);
}